// round 2
// baseline (speedup 1.0000x reference)
#include <cuda_runtime.h>
#include <cuda_fp16.h>

#define BB 256
#define SS 2048
#define EE 64
#define HH 128
#define G4 512   // 4*H

// x_proj scratch: [S][B][4H] fp32 = 1.07 GB
__device__ float g_xp[(size_t)SS * BB * G4];

__device__ __forceinline__ float sigm_f(float x) {
    return 1.0f / (1.0f + __expf(-x));
}
__device__ __forceinline__ float tanh_f(float x) {
    return 2.0f / (1.0f + __expf(-2.0f * x)) - 1.0f;
}

// ---- f32x2 packed-math helpers (sm_103a) ------------------------------------
typedef unsigned long long ull;

__device__ __forceinline__ ull fma2(ull a, ull b, ull c) {
    ull d;
    asm("fma.rn.f32x2 %0, %1, %2, %3;" : "=l"(d) : "l"(a), "l"(b), "l"(c));
    return d;
}
// bf16x2 (lo=k, hi=k+1) -> f32x2 pair (w_k, w_{k+1})
__device__ __forceinline__ ull bf2f2(unsigned int w) {
    unsigned int lo = w << 16;
    unsigned int hi = w & 0xFFFF0000u;
    ull r;
    asm("mov.b64 %0, {%1, %2};" : "=l"(r) : "r"(lo), "r"(hi));
    return r;
}
__device__ __forceinline__ float hsum2(ull v) {
    float x, y;
    asm("mov.b64 {%0, %1}, %2;" : "=f"(x), "=f"(y) : "l"(v));
    return x + y;
}
// pack two fp32 -> bf16x2 (first src -> upper half)
__device__ __forceinline__ unsigned int f2bf2(float hi, float lo) {
    unsigned int r;
    asm("cvt.rn.satfinite.bf16x2.f32 %0, %1, %2;" : "=r"(r) : "f"(hi), "f"(lo));
    return r;
}

// ---------------------------------------------------------------------------
// Kernel 1: x_proj[s][b][f] = dot(inputs[b][s][:], U_all[f][:]) + b_u[f]
// (unchanged — measured at fp32 FMA roofline)
// ---------------------------------------------------------------------------
__global__ __launch_bounds__(256) void xproj_kernel(
    const float* __restrict__ inputs,   // [B][S][E]
    const float* __restrict__ U_all,    // [4H][E]
    const float* __restrict__ b_u)      // [4H]
{
    __shared__ float xT[64 * 68];
    __shared__ float uT[64 * 68];

    const int s      = blockIdx.z;
    const int b_base = blockIdx.y * 64;
    const int f_base = blockIdx.x * 64;
    const int tid    = threadIdx.x;
    const int e      = tid & 63;
    const int r0     = tid >> 6;

    #pragma unroll
    for (int i = 0; i < 16; i++) {
        int r = r0 + i * 4;
        xT[e * 68 + r] = inputs[((size_t)(b_base + r) * SS + s) * EE + e];
        uT[e * 68 + r] = U_all[(size_t)(f_base + r) * EE + e];
    }
    __syncthreads();

    const int bi = (tid >> 4) * 4;
    const int fi = (tid & 15) * 4;

    float acc[4][4];
    #pragma unroll
    for (int i = 0; i < 4; i++)
        #pragma unroll
        for (int j = 0; j < 4; j++) acc[i][j] = 0.0f;

    #pragma unroll 16
    for (int k = 0; k < 64; k++) {
        float4 xv = *reinterpret_cast<const float4*>(&xT[k * 68 + bi]);
        float4 uv = *reinterpret_cast<const float4*>(&uT[k * 68 + fi]);
        float xa[4] = {xv.x, xv.y, xv.z, xv.w};
        float ua[4] = {uv.x, uv.y, uv.z, uv.w};
        #pragma unroll
        for (int i = 0; i < 4; i++)
            #pragma unroll
            for (int j = 0; j < 4; j++)
                acc[i][j] += xa[i] * ua[j];
    }

    float4 bu = *reinterpret_cast<const float4*>(&b_u[f_base + fi]);
    #pragma unroll
    for (int i = 0; i < 4; i++) {
        size_t o = ((size_t)s * BB + (size_t)(b_base + bi + i)) * G4 + f_base + fi;
        float4 v;
        v.x = acc[i][0] + bu.x;
        v.y = acc[i][1] + bu.y;
        v.z = acc[i][2] + bu.z;
        v.w = acc[i][3] + bu.w;
        *reinterpret_cast<float4*>(&g_xp[o]) = v;
    }
}

// ---------------------------------------------------------------------------
// Kernel 2: scan with REGISTER-RESIDENT bf16 weights + packed f32x2 FMA.
// 128 CTAs x 512 threads, 2 batch rows per CTA.
//   Thread t owns gate column n=t (all 128 k, weights in 64 bf16x2 regs)
//   and W_d column j=t&127 for k-quarter kq=t>>7 (16 bf16x2 regs).
//   h/c are read as 16B LDS broadcasts (all lanes same address).
// ---------------------------------------------------------------------------
__global__ __launch_bounds__(512, 1) void scan_kernel(
    const float* __restrict__ TI,      // [B][S]
    const float* __restrict__ W_all,   // [4H][H]
    const float* __restrict__ b_all,   // [4H]
    const float* __restrict__ W_d,     // [H][H]
    const float* __restrict__ b_d,     // [H]
    const float* __restrict__ W_out,   // [1][H]
    const float* __restrict__ b_out,   // [1]
    float* __restrict__ out)           // [B]
{
    __shared__ __align__(16) float hrow[2][HH];     // h per batch row
    __shared__ __align__(16) float crow[2][HH];     // c per batch row
    __shared__ float pre[2][G4];                    // gate preacts per row
    __shared__ float cpart[2][4][HH];               // wd partials per k-quarter
    __shared__ float redbuf[256];

    const int t  = threadIdx.x;
    const int b0 = blockIdx.x * 2;
    const int j  = t & 127;
    const int kq = t >> 7;      // 0..3 : k-quarter for W_d

    // ---- one-time: compress weights into registers (bf16x2 over k-pairs) ----
    unsigned int wb[64];        // W_all row n=t, k = 2p, 2p+1
    #pragma unroll
    for (int p = 0; p < 64; p++) {
        float2 wv = *reinterpret_cast<const float2*>(&W_all[(size_t)t * HH + 2 * p]);
        wb[p] = f2bf2(wv.y, wv.x);
    }
    unsigned int wdb[16];       // W_d row j, k = kq*32 + 2p, +1
    #pragma unroll
    for (int p = 0; p < 16; p++) {
        float2 wv = *reinterpret_cast<const float2*>(&W_d[(size_t)j * HH + kq * 32 + 2 * p]);
        wdb[p] = f2bf2(wv.y, wv.x);
    }

    if (t < 256) {
        hrow[0][j] = 0.0f; crow[0][j] = 0.0f;   // t<128 covers [0][*], 128..255 covers [1][*]
    }
    if (t >= 128 && t < 384) {
        hrow[1][(t - 128) & 127] = 0.0f;
        crow[1][(t - 128) & 127] = 0.0f;
    }

    const float ba = b_all[t];
    float bd_r = 0.0f, wout_r = 0.0f;
    if (t < 256) { bd_r = b_d[j]; wout_r = W_out[j]; }
    const float bo = b_out[0];

    __syncthreads();

    const ulonglong2* h0v = reinterpret_cast<const ulonglong2*>(&hrow[0][0]);
    const ulonglong2* h1v = reinterpret_cast<const ulonglong2*>(&hrow[1][0]);
    const ulonglong2* c0v = reinterpret_cast<const ulonglong2*>(&crow[0][kq * 32]);
    const ulonglong2* c1v = reinterpret_cast<const ulonglong2*>(&crow[1][kq * 32]);

    float out_acc = 0.0f;

    for (int s = 0; s < SS; s++) {
        // xp loads first (DRAM latency hidden under the GEMM)
        size_t xb = ((size_t)s * BB + b0) * G4 + t;
        float xp0 = g_xp[xb];
        float xp1 = g_xp[xb + G4];

        // ---- gate column n = t: 128-k dot for both rows (k-packed f32x2) ----
        ull a0 = 0ULL, a1 = 0ULL;
        #pragma unroll
        for (int q = 0; q < 32; q++) {          // 4 k per iter
            ulonglong2 hh0 = h0v[q];            // (h0[4q],h0[4q+1]) , (h0[4q+2],h0[4q+3])
            ulonglong2 hh1 = h1v[q];
            ull w0 = bf2f2(wb[2 * q]);
            ull w1 = bf2f2(wb[2 * q + 1]);
            a0 = fma2(hh0.x, w0, a0);
            a0 = fma2(hh0.y, w1, a0);
            a1 = fma2(hh1.x, w0, a1);
            a1 = fma2(hh1.y, w1, a1);
        }

        // ---- W_d column j, k-quarter kq: 32-k partial dot for both rows ----
        ull d0 = 0ULL, d1 = 0ULL;
        #pragma unroll
        for (int q = 0; q < 8; q++) {
            ulonglong2 cc0 = c0v[q];
            ulonglong2 cc1 = c1v[q];
            ull w0 = bf2f2(wdb[2 * q]);
            ull w1 = bf2f2(wdb[2 * q + 1]);
            d0 = fma2(cc0.x, w0, d0);
            d0 = fma2(cc0.y, w1, d0);
            d1 = fma2(cc1.x, w0, d1);
            d1 = fma2(cc1.y, w1, d1);
        }

        pre[0][t] = hsum2(a0) + ba + xp0;
        pre[1][t] = hsum2(a1) + ba + xp1;
        cpart[0][kq][j] = hsum2(d0);
        cpart[1][kq][j] = hsum2(d1);
        __syncthreads();

        // ---- gating: threads 0..255, (m, j) ----
        if (t < 256) {
            const int m = t >> 7;
            float fg = sigm_f(pre[m][j]);
            float ig = sigm_f(pre[m][128 + j]);
            float og = sigm_f(pre[m][256 + j]);
            float ct = sigm_f(pre[m][384 + j]);
            float cp = cpart[m][0][j] + cpart[m][1][j]
                     + cpart[m][2][j] + cpart[m][3][j] + bd_r;
            float cs1  = tanh_f(cp);
            float d    = TI[(size_t)(b0 + m) * SS + s];
            float cold = crow[m][j];
            float cadj = (cold - cs1) + cs1 * d;
            float cnew = fg * cadj + ig * ct;
            float hnew = og * tanh_f(cnew);
            crow[m][j] = cnew;
            hrow[m][j] = hnew;
            out_acc += hnew * wout_r;
        }
        __syncthreads();
    }

    // ---- out[b] = sum_s h_s @ W_out + S * b_out ----
    if (t < 256) redbuf[t] = out_acc;
    __syncthreads();
    if (t == 0) {
        float s0 = 0.0f;
        for (int k = 0; k < 128; k++) s0 += redbuf[k];
        out[b0] = s0 + (float)SS * bo;
    }
    if (t == 1) {
        float s1 = 0.0f;
        for (int k = 0; k < 128; k++) s1 += redbuf[128 + k];
        out[b0 + 1] = s1 + (float)SS * bo;
    }
}

// ---------------------------------------------------------------------------
extern "C" void kernel_launch(void* const* d_in, const int* in_sizes, int n_in,
                              void* d_out, int out_size)
{
    const float* inputs = (const float*)d_in[0];
    const float* TI     = (const float*)d_in[1];
    const float* W_all  = (const float*)d_in[2];
    const float* b_all  = (const float*)d_in[3];
    const float* U_all  = (const float*)d_in[4];
    const float* b_u    = (const float*)d_in[5];
    const float* W_d    = (const float*)d_in[6];
    const float* b_d    = (const float*)d_in[7];
    const float* W_out  = (const float*)d_in[8];
    const float* b_out  = (const float*)d_in[9];
    float* out = (float*)d_out;

    xproj_kernel<<<dim3(8, 4, SS), 256>>>(inputs, U_all, b_u);
    scan_kernel<<<128, 512>>>(TI, W_all, b_all, W_d, b_d, W_out, b_out, out);
}

// round 3
// speedup vs baseline: 2.2426x; 2.2426x over previous
#include <cuda_runtime.h>
#include <cuda_fp16.h>

#define BB 256
#define SS 2048
#define EE 64
#define HH 128
#define G4 512   // 4*H

// x_proj scratch: [S][B][4H] fp32 = 1.07 GB
__device__ float g_xp[(size_t)SS * BB * G4];

__device__ __forceinline__ float sigm_f(float x) {
    return 1.0f / (1.0f + __expf(-x));
}
__device__ __forceinline__ float tanh_f(float x) {
    return 2.0f / (1.0f + __expf(-2.0f * x)) - 1.0f;
}

// ---- f32x2 packed-math helpers (sm_103a) ------------------------------------
typedef unsigned long long ull;

__device__ __forceinline__ ull fma2(ull a, ull b, ull c) {
    ull d;
    asm("fma.rn.f32x2 %0, %1, %2, %3;" : "=l"(d) : "l"(a), "l"(b), "l"(c));
    return d;
}
// bf16x2 (lo half = w_k, hi half = w_{k+1}) -> f32x2 (w_k, w_{k+1})
__device__ __forceinline__ ull bf2f2(unsigned int w) {
    unsigned int lo = w << 16;
    unsigned int hi = w & 0xFFFF0000u;
    ull r;
    asm("mov.b64 %0, {%1, %2};" : "=l"(r) : "r"(lo), "r"(hi));
    return r;
}
__device__ __forceinline__ float hsum2(ull v) {
    float x, y;
    asm("mov.b64 {%0, %1}, %2;" : "=f"(x), "=f"(y) : "l"(v));
    return x + y;
}
__device__ __forceinline__ unsigned int f2bf2(float hi, float lo) {
    unsigned int r;
    asm("cvt.rn.satfinite.bf16x2.f32 %0, %1, %2;" : "=r"(r) : "f"(hi), "f"(lo));
    return r;
}
__device__ __forceinline__ ull dup2(float x) {
    ull r;
    asm("mov.b64 %0, {%1, %1};" : "=l"(r) : "f"(x));
    return r;
}

// ---------------------------------------------------------------------------
// Kernel 1: x_proj[s][b][f] = dot(inputs[b][s][:], U_all[f][:]) + b_u[f]
// f32x2-packed over the f dimension (2 MACs/FMA-slot)
// ---------------------------------------------------------------------------
__global__ __launch_bounds__(256) void xproj_kernel(
    const float* __restrict__ inputs,   // [B][S][E]
    const float* __restrict__ U_all,    // [4H][E]
    const float* __restrict__ b_u)      // [4H]
{
    __shared__ float xT[64 * 68];  // [e][b]
    __shared__ float uT[64 * 68];  // [e][f]

    const int s      = blockIdx.z;
    const int b_base = blockIdx.y * 64;
    const int f_base = blockIdx.x * 64;
    const int tid    = threadIdx.x;
    const int e      = tid & 63;
    const int r0     = tid >> 6;

    #pragma unroll
    for (int i = 0; i < 16; i++) {
        int r = r0 + i * 4;
        xT[e * 68 + r] = inputs[((size_t)(b_base + r) * SS + s) * EE + e];
        uT[e * 68 + r] = U_all[(size_t)(f_base + r) * EE + e];
    }
    __syncthreads();

    const int bi = (tid >> 4) * 4;
    const int fi = (tid & 15) * 4;

    ull acc[4][2];
    #pragma unroll
    for (int i = 0; i < 4; i++) { acc[i][0] = 0ULL; acc[i][1] = 0ULL; }

    #pragma unroll 16
    for (int k = 0; k < 64; k++) {
        float4 xv = *reinterpret_cast<const float4*>(&xT[k * 68 + bi]);
        ulonglong2 uvp = *reinterpret_cast<const ulonglong2*>(&uT[k * 68 + fi]);
        float xa[4] = {xv.x, xv.y, xv.z, xv.w};
        #pragma unroll
        for (int i = 0; i < 4; i++) {
            ull xx = dup2(xa[i]);
            acc[i][0] = fma2(xx, uvp.x, acc[i][0]);
            acc[i][1] = fma2(xx, uvp.y, acc[i][1]);
        }
    }

    float4 bu = *reinterpret_cast<const float4*>(&b_u[f_base + fi]);
    #pragma unroll
    for (int i = 0; i < 4; i++) {
        size_t o = ((size_t)s * BB + (size_t)(b_base + bi + i)) * G4 + f_base + fi;
        float a0, a1, a2, a3;
        asm("mov.b64 {%0, %1}, %2;" : "=f"(a0), "=f"(a1) : "l"(acc[i][0]));
        asm("mov.b64 {%0, %1}, %2;" : "=f"(a2), "=f"(a3) : "l"(acc[i][1]));
        float4 v;
        v.x = a0 + bu.x;
        v.y = a1 + bu.y;
        v.z = a2 + bu.z;
        v.w = a3 + bu.w;
        *reinterpret_cast<float4*>(&g_xp[o]) = v;
    }
}

// ---------------------------------------------------------------------------
// Kernel 2: scan. 128 CTAs x 512 threads, 2 batch rows per CTA.
// Transposed bf16x2 weights in SMEM (lane-consecutive, conflict-free).
// Thread t = (c = t&127, kq = t>>7): computes quarter-k partials for the 4
// gate columns {g*128+c} and for W_d column c, both batch rows.
// ---------------------------------------------------------------------------
// dynamic SMEM byte offsets
#define SM_WG     0                      // 64*512 uints  = 131072 B
#define SM_WD     131072                 // 64*128 uints  =  32768 B
#define SM_H      163840                 // 2*128 floats  =   1024 B
#define SM_C      164864                 // 2*128 floats  =   1024 B
#define SM_PREG   165888                 // 4*4*2*128 f   =  16384 B
#define SM_CPART  182272                 // 4*2*128 f     =   4096 B
#define SM_RED    186368                 // 256 floats    =   1024 B
#define SMEM_BYTES 187392

__global__ __launch_bounds__(512, 1) void scan_kernel(
    const float* __restrict__ TI,      // [B][S]
    const float* __restrict__ W_all,   // [4H][H]
    const float* __restrict__ b_all,   // [4H]
    const float* __restrict__ W_d,     // [H][H]
    const float* __restrict__ b_d,     // [H]
    const float* __restrict__ W_out,   // [1][H]
    const float* __restrict__ b_out,   // [1]
    float* __restrict__ out)           // [B]
{
    extern __shared__ char smem[];
    unsigned int* wg  = reinterpret_cast<unsigned int*>(smem + SM_WG);
    unsigned int* wdx = reinterpret_cast<unsigned int*>(smem + SM_WD);
    float* hb    = reinterpret_cast<float*>(smem + SM_H);     // [2][128]
    float* cb    = reinterpret_cast<float*>(smem + SM_C);     // [2][128]
    float* preg  = reinterpret_cast<float*>(smem + SM_PREG);  // [(kq*4+g)*2+m][128]
    float* cpart = reinterpret_cast<float*>(smem + SM_CPART); // [kq*2+m][128]
    float* red   = reinterpret_cast<float*>(smem + SM_RED);

    const int t  = threadIdx.x;
    const int b0 = blockIdx.x * 2;
    const int c  = t & 127;
    const int kq = t >> 7;      // 0..3

    // ---- one-time: pack transposed weights into SMEM ----
    // wg[r*512 + g*128 + c] = bf16x2( W_all[g*128+c][2r], W_all[g*128+c][2r+1] )
    for (int u = t; u < 64 * 512; u += 512) {
        int r = u >> 9, rem = u & 511;
        int gg = rem >> 7, cc = rem & 127;
        float2 wv = *reinterpret_cast<const float2*>(&W_all[(size_t)(gg * 128 + cc) * HH + 2 * r]);
        wg[u] = f2bf2(wv.y, wv.x);
    }
    // wdx[r*128 + j] = bf16x2( W_d[j][2r], W_d[j][2r+1] )
    for (int u = t; u < 64 * 128; u += 512) {
        int r = u >> 7, jj = u & 127;
        float2 wv = *reinterpret_cast<const float2*>(&W_d[(size_t)jj * HH + 2 * r]);
        wdx[u] = f2bf2(wv.y, wv.x);
    }
    if (t < 256) { hb[t] = 0.0f; cb[t] = 0.0f; }

    // per-thread constants for phase B (threads 0..255: m = t>>7, j = c)
    float ba_r[4], bd_r = 0.0f, wout_r = 0.0f;
    if (t < 256) {
        #pragma unroll
        for (int g = 0; g < 4; g++) ba_r[g] = b_all[g * 128 + c];
        bd_r = b_d[c];
        wout_r = W_out[c];
    }
    const float bo = b_out[0];

    __syncthreads();

    // streaming pointers (weights: lane-consecutive; h/c: warp-broadcast)
    const unsigned int* wgt = wg  + (kq * 16) * 512 + c;   // (p,g) at wgt[(p*4+g)*128]
    const unsigned int* wdt = wdx + (kq * 16) * 128 + c;   // p at wdt[p*128]
    const ulonglong2* h0v = reinterpret_cast<const ulonglong2*>(hb + kq * 32);
    const ulonglong2* h1v = reinterpret_cast<const ulonglong2*>(hb + 128 + kq * 32);
    const ulonglong2* c0v = reinterpret_cast<const ulonglong2*>(cb + kq * 32);
    const ulonglong2* c1v = reinterpret_cast<const ulonglong2*>(cb + 128 + kq * 32);

    float out_acc = 0.0f;

    for (int s = 0; s < SS; s++) {
        // prefetch phase-B globals early (hidden under phase A)
        float xpv[4], ti = 0.0f;
        if (t < 256) {
            const int m = t >> 7;
            size_t xb = ((size_t)s * BB + b0 + m) * G4 + c;
            #pragma unroll
            for (int g = 0; g < 4; g++) xpv[g] = g_xp[xb + g * 128];
            ti = TI[(size_t)(b0 + m) * SS + s];
        }

        // ---- Phase A: quarter-k partial dots ----
        ull acc0[4] = {0ULL, 0ULL, 0ULL, 0ULL};   // per gate, row 0
        ull acc1[4] = {0ULL, 0ULL, 0ULL, 0ULL};   // per gate, row 1
        ull d0 = 0ULL, d1 = 0ULL;

        #pragma unroll
        for (int p2 = 0; p2 < 8; p2++) {
            ulonglong2 hh0 = h0v[p2];
            ulonglong2 hh1 = h1v[p2];
            #pragma unroll
            for (int g = 0; g < 4; g++) {
                ull wA = bf2f2(wgt[(8 * p2 + g) * 128]);
                ull wB = bf2f2(wgt[(8 * p2 + 4 + g) * 128]);
                acc0[g] = fma2(hh0.x, wA, acc0[g]);
                acc0[g] = fma2(hh0.y, wB, acc0[g]);
                acc1[g] = fma2(hh1.x, wA, acc1[g]);
                acc1[g] = fma2(hh1.y, wB, acc1[g]);
            }
            ulonglong2 cc0 = c0v[p2];
            ulonglong2 cc1 = c1v[p2];
            ull dA = bf2f2(wdt[(2 * p2) * 128]);
            ull dB = bf2f2(wdt[(2 * p2 + 1) * 128]);
            d0 = fma2(cc0.x, dA, d0);
            d0 = fma2(cc0.y, dB, d0);
            d1 = fma2(cc1.x, dA, d1);
            d1 = fma2(cc1.y, dB, d1);
        }

        #pragma unroll
        for (int g = 0; g < 4; g++) {
            preg[((kq * 4 + g) * 2 + 0) * 128 + c] = hsum2(acc0[g]);
            preg[((kq * 4 + g) * 2 + 1) * 128 + c] = hsum2(acc1[g]);
        }
        cpart[(kq * 2 + 0) * 128 + c] = hsum2(d0);
        cpart[(kq * 2 + 1) * 128 + c] = hsum2(d1);
        __syncthreads();

        // ---- Phase B: gating (threads 0..255; (m, j) = (t>>7, c)) ----
        if (t < 256) {
            const int m = t >> 7;
            float pg[4];
            #pragma unroll
            for (int g = 0; g < 4; g++) {
                pg[g] = preg[((0 * 4 + g) * 2 + m) * 128 + c]
                      + preg[((1 * 4 + g) * 2 + m) * 128 + c]
                      + preg[((2 * 4 + g) * 2 + m) * 128 + c]
                      + preg[((3 * 4 + g) * 2 + m) * 128 + c]
                      + ba_r[g] + xpv[g];
            }
            float fg = sigm_f(pg[0]);
            float ig = sigm_f(pg[1]);
            float og = sigm_f(pg[2]);
            float ct = sigm_f(pg[3]);
            float cp = cpart[(0 * 2 + m) * 128 + c] + cpart[(1 * 2 + m) * 128 + c]
                     + cpart[(2 * 2 + m) * 128 + c] + cpart[(3 * 2 + m) * 128 + c] + bd_r;
            float cs1  = tanh_f(cp);
            float cold = cb[m * 128 + c];
            float cadj = (cold - cs1) + cs1 * ti;
            float cnew = fg * cadj + ig * ct;
            float hnew = og * tanh_f(cnew);
            cb[m * 128 + c] = cnew;
            hb[m * 128 + c] = hnew;
            out_acc += hnew * wout_r;
        }
        __syncthreads();
    }

    // ---- out[b] = sum_s h_s @ W_out + S * b_out ----
    if (t < 256) red[t] = out_acc;
    __syncthreads();
    if (t == 0) {
        float s0 = 0.0f;
        for (int k = 0; k < 128; k++) s0 += red[k];
        out[b0] = s0 + (float)SS * bo;
    }
    if (t == 1) {
        float s1 = 0.0f;
        for (int k = 0; k < 128; k++) s1 += red[128 + k];
        out[b0 + 1] = s1 + (float)SS * bo;
    }
}

// ---------------------------------------------------------------------------
extern "C" void kernel_launch(void* const* d_in, const int* in_sizes, int n_in,
                              void* d_out, int out_size)
{
    const float* inputs = (const float*)d_in[0];
    const float* TI     = (const float*)d_in[1];
    const float* W_all  = (const float*)d_in[2];
    const float* b_all  = (const float*)d_in[3];
    const float* U_all  = (const float*)d_in[4];
    const float* b_u    = (const float*)d_in[5];
    const float* W_d    = (const float*)d_in[6];
    const float* b_d    = (const float*)d_in[7];
    const float* W_out  = (const float*)d_in[8];
    const float* b_out  = (const float*)d_in[9];
    float* out = (float*)d_out;

    xproj_kernel<<<dim3(8, 4, SS), 256>>>(inputs, U_all, b_u);

    cudaFuncSetAttribute(scan_kernel,
                         cudaFuncAttributeMaxDynamicSharedMemorySize, SMEM_BYTES);
    scan_kernel<<<128, 512, SMEM_BYTES>>>(TI, W_all, b_all, W_d, b_d,
                                          W_out, b_out, out);
}